// round 10
// baseline (speedup 1.0000x reference)
#include <cuda_runtime.h>
#include <cuda_bf16.h>
#include <math.h>

#define B_  256
#define T_  256
#define E_  64
#define N_  512
#define V_  128
#define G4  2048   // 4*N
#define NBLK 128
#define NW2 (N_ / 2)   // 256 packed words per row

#define KS_BF 520   // Whs stride in bf16: [col][k], padded
#define KS_W  260
#define HA_BF 72    // hA stride in bf16: [row][k] per 64-k chunk, padded
#define HA_W  36
#define Z_STRIDE 68 // z-exchange float stride

// SMEM byte offsets (recurrence)
#define OFF_WHI 0
#define OFF_WLO (64 * KS_BF * 2)                 // 66560
#define OFF_HA  (2 * 64 * KS_BF * 2)             // 133120
#define HA_BYTES (64 * HA_BF * 2)                // 9216
#define SMEM_TOTAL_LSTM (OFF_HA + 4 * HA_BYTES)  // 169984

// GEMM kernels (input/out): 4 planes of [128][36 words]
#define GW 36
#define PLANE (128 * GW)
#define SMEM_GEMM (4 * PLANE * 4)                 // 73728 bytes

// ---- scratch (static device memory; no allocations) ----
__device__ float g_xz[(size_t)T_ * B_ * G4];            // [T,B,4N] input proj (+bias)
__device__ unsigned g_hshi[(size_t)(T_ + 1) * B_ * NW2]; // h as bf16 hi plane; [t][b][n/2]
__device__ unsigned g_hslo[(size_t)(T_ + 1) * B_ * NW2]; // h as bf16 lo plane
__device__ unsigned g_flags[NBLK * 32];                  // grid barrier flags

// ---------------------------------------------------------------------------
__device__ __forceinline__ float sigf(float x) {
    return __fdividef(1.f, 1.f + __expf(-x));
}

__device__ __forceinline__ float tanhf_fast(float x) {
    float t = __expf(-2.f * fabsf(x));
    float r = __fdividef(1.f - t, 1.f + t);
    return copysignf(r, x);
}

__device__ __forceinline__ void mma_bf16(float* d, const unsigned* a, const unsigned* b) {
    asm volatile(
        "mma.sync.aligned.m16n8k16.row.col.f32.bf16.bf16.f32 "
        "{%0,%1,%2,%3}, {%4,%5,%6,%7}, {%8,%9}, {%0,%1,%2,%3};"
        : "+f"(d[0]), "+f"(d[1]), "+f"(d[2]), "+f"(d[3])
        : "r"(a[0]), "r"(a[1]), "r"(a[2]), "r"(a[3]), "r"(b[0]), "r"(b[1]));
}

__device__ __forceinline__ void bf16_split(float x, __nv_bfloat16& hi, __nv_bfloat16& lo) {
    hi = __float2bfloat16(x);
    lo = __float2bfloat16(x - __bfloat162float(hi));
}

__device__ __forceinline__ unsigned pack_bf2(__nv_bfloat16 lo, __nv_bfloat16 hi) {
    unsigned short ul = __bfloat16_as_ushort(lo);
    unsigned short uh = __bfloat16_as_ushort(hi);
    return (unsigned)ul | ((unsigned)uh << 16);
}

__device__ __forceinline__ void split4(float4 v, uint2& hw, uint2& lw) {
    __nv_bfloat16 h0, l0, h1, l1, h2, l2, h3, l3;
    bf16_split(v.x, h0, l0); bf16_split(v.y, h1, l1);
    bf16_split(v.z, h2, l2); bf16_split(v.w, h3, l3);
    hw = make_uint2(pack_bf2(h0, h1), pack_bf2(h2, h3));
    lw = make_uint2(pack_bf2(l0, l1), pack_bf2(l2, l3));
}

extern __shared__ char smem_raw[];

// ---------------------------------------------------------------------------
// init: split h_0 into plane[0], reset barrier flags
// ---------------------------------------------------------------------------
__global__ void init_kernel(const float* __restrict__ h0) {
    int i = blockIdx.x * blockDim.x + threadIdx.x;
    if (i < B_ * NW2) {
        float2 v = *(const float2*)(h0 + 2 * i);
        __nv_bfloat16 ha, la, hb, lb;
        bf16_split(v.x, ha, la); bf16_split(v.y, hb, lb);
        g_hshi[i] = pack_bf2(ha, hb);
        g_hslo[i] = pack_bf2(la, lb);
    }
    if (i < NBLK) g_flags[i * 32] = 0u;
}

// ---------------------------------------------------------------------------
// bf16x2 tensor-core GEMM core for input/out GEMMs
// ---------------------------------------------------------------------------
__device__ __forceinline__ void gemm_chunk(const unsigned* AhiW, const unsigned* AloW,
                                           const unsigned* BhiW, const unsigned* BloW,
                                           int wr, int wc, int g4r, int lk,
                                           float acc[2][8][4]) {
#pragma unroll
    for (int k16 = 0; k16 < 4; k16++) {
        unsigned aHi[2][4], aLo[2][4];
#pragma unroll
        for (int f = 0; f < 2; f++) {
            int aw = (wr + f * 16 + g4r) * GW + lk + k16 * 8;
            aHi[f][0] = AhiW[aw];          aHi[f][1] = AhiW[aw + 8 * GW];
            aHi[f][2] = AhiW[aw + 4];      aHi[f][3] = AhiW[aw + 8 * GW + 4];
            aLo[f][0] = AloW[aw];          aLo[f][1] = AloW[aw + 8 * GW];
            aLo[f][2] = AloW[aw + 4];      aLo[f][3] = AloW[aw + 8 * GW + 4];
        }
#pragma unroll
        for (int sub = 0; sub < 8; sub++) {
            int col = wc + sub * 8 + g4r;
            int bw  = col * GW + lk + k16 * 8;
            unsigned bHi[2], bLo[2];
            bHi[0] = BhiW[bw]; bHi[1] = BhiW[bw + 4];
            bLo[0] = BloW[bw]; bLo[1] = BloW[bw + 4];
#pragma unroll
            for (int f = 0; f < 2; f++) {
                mma_bf16(acc[f][sub], aHi[f], bHi);
                mma_bf16(acc[f][sub], aHi[f], bLo);
                mma_bf16(acc[f][sub], aLo[f], bHi);
            }
        }
    }
}

// ---------------------------------------------------------------------------
// Kernel A (tensor): xz[r][g] = bias[g] + sum_e emb[X[b][t]][e] * Wx[e][g]
// ---------------------------------------------------------------------------
__global__ void __launch_bounds__(256)
input_gemm_tc(const int*   __restrict__ X,
              const float* __restrict__ emb,
              const float* __restrict__ Wx,
              const float* __restrict__ bias) {
    unsigned* AhiW = (unsigned*)smem_raw;
    unsigned* AloW = AhiW + PLANE;
    unsigned* BhiW = AloW + PLANE;
    unsigned* BloW = BhiW + PLANE;
    __shared__ int xid[128];

    const int tid  = threadIdx.x;
    const int r0   = blockIdx.y * 128;
    const int g0   = blockIdx.x * 128;
    const int lane = tid & 31;
    const int wid  = tid >> 5;
    const int wr   = (wid & 3) * 32;
    const int wc   = (wid >> 2) * 64;
    const int g4r  = lane >> 2;
    const int lk   = lane & 3;
    const int lx2  = lk * 2;

    if (tid < 128) {
        int r = r0 + tid;
        xid[tid] = X[(r & 255) * T_ + (r >> 8)];
    }
    __syncthreads();

    {
        int row = tid >> 1;
        const float* src = emb + (size_t)xid[row] * E_;
        int qb = (tid & 1) * 8;
#pragma unroll
        for (int q = 0; q < 8; q++) {
            float4 v = *(const float4*)(src + (qb + q) * 4);
            uint2 hw, lw;
            split4(v, hw, lw);
            int widx = row * GW + (qb + q) * 2;
            *(uint2*)(AhiW + widx) = hw;
            *(uint2*)(AloW + widx) = lw;
        }
    }
    {
        int c = tid & 127, khalf = tid >> 7;
#pragma unroll
        for (int kk = 0; kk < 16; kk++) {
            int k0 = khalf * 32 + kk * 2;
            float a = Wx[(size_t)k0 * G4 + g0 + c];
            float b = Wx[(size_t)(k0 + 1) * G4 + g0 + c];
            __nv_bfloat16 ha, la, hb, lb;
            bf16_split(a, ha, la); bf16_split(b, hb, lb);
            int widx = c * GW + khalf * 16 + kk;
            BhiW[widx] = pack_bf2(ha, hb);
            BloW[widx] = pack_bf2(la, lb);
        }
    }
    __syncthreads();

    float acc[2][8][4];
#pragma unroll
    for (int f = 0; f < 2; f++)
#pragma unroll
        for (int s = 0; s < 8; s++)
#pragma unroll
            for (int i = 0; i < 4; i++) acc[f][s][i] = 0.f;

    gemm_chunk(AhiW, AloW, BhiW, BloW, wr, wc, g4r, lk, acc);

#pragma unroll
    for (int f = 0; f < 2; f++) {
        int rlo = r0 + wr + f * 16 + g4r;
#pragma unroll
        for (int sub = 0; sub < 8; sub++) {
            int g = g0 + wc + sub * 8 + lx2;
            float2 bb = *(const float2*)(bias + g);
            *(float2*)(g_xz + (size_t)rlo * G4 + g) =
                make_float2(acc[f][sub][0] + bb.x, acc[f][sub][1] + bb.y);
            *(float2*)(g_xz + (size_t)(rlo + 8) * G4 + g) =
                make_float2(acc[f][sub][2] + bb.x, acc[f][sub][3] + bb.y);
        }
    }
}

// ---------------------------------------------------------------------------
// Persistent LSTM recurrence (R9 structure) with producer-split h:
//  h stored only as bf16 hi/lo planes; staging is a raw uint4 copy.
//  Discrete LDS fragment loads (NOT ldmatrix — R8 showed LDSM regresses here).
// ---------------------------------------------------------------------------
__global__ void __launch_bounds__(256, 1)
lstm_persistent(const float* __restrict__ Wh, const float* __restrict__ c0) {
    __nv_bfloat16* WhHi = (__nv_bfloat16*)(smem_raw + OFF_WHI);
    __nv_bfloat16* WhLo = (__nv_bfloat16*)(smem_raw + OFF_WLO);
    const unsigned* WhHiW = (const unsigned*)WhHi;
    const unsigned* WhLoW = (const unsigned*)WhLo;

    char* hBase = smem_raw + OFF_HA;   // buf0: hi,lo ; buf1: hi,lo

    const int tid  = threadIdx.x;
    const int bid  = blockIdx.x;
    const int cg   = bid & 31;          // n-group
    const int rg   = bid >> 5;          // row-group
    const int n0   = cg * 16;
    const int r0   = rg * 64;
    const int lane = tid & 31;
    const int wid  = tid >> 5;
    const int wr   = (wid & 3) * 16;    // warp row offset
    const int wc   = (wid >> 2) * 32;   // warp col offset
    const int g4r  = lane >> 2;
    const int lk   = lane & 3;
    const int lx2  = lk * 2;

    // ---- load + split Wh slice once: WhHi/WhLo[col][k], col = g*16+j ----
    for (int idx = tid; idx < 512 * 16; idx += 256) {
        int k = idx >> 4, q = idx & 15;
        int g = q >> 2, jj = (q & 3) * 4;
        float4 w = *(const float4*)(Wh + (size_t)k * G4 + g * N_ + n0 + jj);
        int cb = g * 16 + jj;
        __nv_bfloat16 hi, lo;
        bf16_split(w.x, hi, lo); WhHi[(cb + 0) * KS_BF + k] = hi; WhLo[(cb + 0) * KS_BF + k] = lo;
        bf16_split(w.y, hi, lo); WhHi[(cb + 1) * KS_BF + k] = hi; WhLo[(cb + 1) * KS_BF + k] = lo;
        bf16_split(w.z, hi, lo); WhHi[(cb + 2) * KS_BF + k] = hi; WhLo[(cb + 2) * KS_BF + k] = lo;
        bf16_split(w.w, hi, lo); WhHi[(cb + 3) * KS_BF + k] = hi; WhLo[(cb + 3) * KS_BF + k] = lo;
    }

    // ---- cell state in registers ----
    const int prow = tid >> 2;
    const int pj0  = (tid & 3) * 4;
    float4 creg = *(const float4*)(c0 + (size_t)(r0 + prow) * N_ + n0 + pj0);

    __syncthreads();

    // staging mapping: 2 planes x 64 rows x 2 halves; 4 uint4 per thread/chunk
    const int splane = tid >> 7;           // 0 = hi, 1 = lo
    const int srow   = (tid >> 1) & 63;
    const int shalf  = tid & 1;            // words [shalf*16, +16)
    const int sgoff  = (r0 + srow) * NW2 + shalf * 16;
    const int ssoff  = srow * HA_W + shalf * 16;

    const int rlo = r0 + wr + g4r;         // mma row base

    // ---- xz prefetch (t = 0) ----
    float2 xzp[8];
#pragma unroll
    for (int sub = 0; sub < 4; sub++) {
        int c    = wc + sub * 8 + lx2;
        int gate = c >> 4, jj = c & 15;
        size_t base = (size_t)gate * N_ + n0 + jj;
        xzp[sub * 2 + 0] = __ldcg((const float2*)(g_xz + base + (size_t)rlo * G4));
        xzp[sub * 2 + 1] = __ldcg((const float2*)(g_xz + base + (size_t)(rlo + 8) * G4));
    }

    for (int t = 0; t < T_; t++) {
        const unsigned* __restrict__ gin =
            (splane ? g_hslo : g_hshi) + (size_t)t * B_ * NW2;
        unsigned* __restrict__ outHi = g_hshi + (size_t)(t + 1) * B_ * NW2;
        unsigned* __restrict__ outLo = g_hslo + (size_t)(t + 1) * B_ * NW2;

        // ---- acc init from prefetched xz ----
        float acc[4][4];
#pragma unroll
        for (int sub = 0; sub < 4; sub++) {
            acc[sub][0] = xzp[sub * 2 + 0].x; acc[sub][1] = xzp[sub * 2 + 0].y;
            acc[sub][2] = xzp[sub * 2 + 1].x; acc[sub][3] = xzp[sub * 2 + 1].y;
        }

        // ---- GEMM over K=512 in 8 chunks of 64, double-buffered copy staging ----
        uint4 pf[4];
#pragma unroll
        for (int q = 0; q < 4; q++)
            pf[q] = __ldcg((const uint4*)(gin + sgoff + q * 4));

        for (int kc = 0; kc < 8; kc++) {
            unsigned* dst = (unsigned*)(hBase + (kc & 1) * 2 * HA_BYTES + splane * HA_BYTES);
#pragma unroll
            for (int q = 0; q < 4; q++)
                *(uint4*)(dst + ssoff + q * 4) = pf[q];
            if (kc < 7) {
#pragma unroll
                for (int q = 0; q < 4; q++)
                    pf[q] = __ldcg((const uint4*)(gin + sgoff + (kc + 1) * 32 + q * 4));
            }
            __syncthreads();

            unsigned* hHiW = (unsigned*)(hBase + (kc & 1) * 2 * HA_BYTES);
            unsigned* hLoW = hHiW + HA_BYTES / 4;
            const int aBase = (wr + g4r) * HA_W + lk;
#pragma unroll
            for (int k16 = 0; k16 < 4; k16++) {
                const int aw = aBase + k16 * 8;
                unsigned aHi[4], aLo[4];
                aHi[0] = hHiW[aw];              aHi[1] = hHiW[aw + 8 * HA_W];
                aHi[2] = hHiW[aw + 4];          aHi[3] = hHiW[aw + 8 * HA_W + 4];
                aLo[0] = hLoW[aw];              aLo[1] = hLoW[aw + 8 * HA_W];
                aLo[2] = hLoW[aw + 4];          aLo[3] = hLoW[aw + 8 * HA_W + 4];
                const int kAbs = kc * 32 + lk + k16 * 8;
#pragma unroll
                for (int sub = 0; sub < 4; sub++) {
                    const int col = wc + sub * 8 + g4r;
                    const int bw  = col * KS_W + kAbs;
                    unsigned bHi[2], bLo[2];
                    bHi[0] = WhHiW[bw]; bHi[1] = WhHiW[bw + 4];
                    bLo[0] = WhLoW[bw]; bLo[1] = WhLoW[bw + 4];
                    mma_bf16(acc[sub], aHi, bHi);
                    mma_bf16(acc[sub], aHi, bLo);
                    mma_bf16(acc[sub], aLo, bHi);
                }
            }
            // no tail sync: next store targets the other buffer
        }

        // ---- exchange z through SMEM ----
        float* zs = (float*)hBase;
        {
            const int rl = wr + g4r;
#pragma unroll
            for (int sub = 0; sub < 4; sub++) {
                int c = wc + sub * 8 + lx2;
                *(float2*)(zs + (size_t)rl * Z_STRIDE + c)       = make_float2(acc[sub][0], acc[sub][1]);
                *(float2*)(zs + (size_t)(rl + 8) * Z_STRIDE + c) = make_float2(acc[sub][2], acc[sub][3]);
            }
        }
        __syncthreads();

        // ---- pointwise gates + c/h update; split h once at producer ----
        {
            const float* zr = zs + (size_t)prow * Z_STRIDE + pj0;
            float4 zi = *(const float4*)(zr + 0);
            float4 zf = *(const float4*)(zr + 16);
            float4 zg = *(const float4*)(zr + 32);
            float4 zo = *(const float4*)(zr + 48);

            float4 hv;
            creg.x = sigf(zf.x) * creg.x + sigf(zi.x) * tanhf_fast(zg.x); hv.x = sigf(zo.x) * tanhf_fast(creg.x);
            creg.y = sigf(zf.y) * creg.y + sigf(zi.y) * tanhf_fast(zg.y); hv.y = sigf(zo.y) * tanhf_fast(creg.y);
            creg.z = sigf(zf.z) * creg.z + sigf(zi.z) * tanhf_fast(zg.z); hv.z = sigf(zo.z) * tanhf_fast(creg.z);
            creg.w = sigf(zf.w) * creg.w + sigf(zi.w) * tanhf_fast(zg.w); hv.w = sigf(zo.w) * tanhf_fast(creg.w);

            uint2 hw, lw;
            split4(hv, hw, lw);
            size_t woff = (size_t)(r0 + prow) * NW2 + ((n0 + pj0) >> 1);
            *(uint2*)(outHi + woff) = hw;
            *(uint2*)(outLo + woff) = lw;
        }

        // ---- prefetch next step's xz (latency hidden under barrier poll) ----
        if (t + 1 < T_) {
#pragma unroll
            for (int sub = 0; sub < 4; sub++) {
                int c    = wc + sub * 8 + lx2;
                int gate = c >> 4, jj = c & 15;
                size_t base = (size_t)(t + 1) * B_ * G4 + (size_t)gate * N_ + n0 + jj;
                xzp[sub * 2 + 0] = __ldcg((const float2*)(g_xz + base + (size_t)rlo * G4));
                xzp[sub * 2 + 1] = __ldcg((const float2*)(g_xz + base + (size_t)(rlo + 8) * G4));
            }
        }

        // ---- full-grid barrier (all 128 blocks resident) ----
        __threadfence();
        __syncthreads();
        if (tid == 0) {
            asm volatile("st.global.release.gpu.u32 [%0], %1;"
                         :: "l"(&g_flags[bid * 32]), "r"((unsigned)(t + 1)) : "memory");
        }
        if (tid < NBLK) {
            unsigned v;
            do {
                asm volatile("ld.global.acquire.gpu.u32 %0, [%1];"
                             : "=r"(v) : "l"(&g_flags[tid * 32]) : "memory");
                if (v >= (unsigned)(t + 1)) break;
                __nanosleep(20);
            } while (true);
        }
        __syncthreads();
    }
}

// ---------------------------------------------------------------------------
// Kernel D (tensor): logits[b][t][v] = bd[v] + sum_n hs[t][b][n] * Wd[n][v]
//   A-staging is a raw copy from the bf16 hi/lo planes (rows of one block
//   share a single t; plane[t+1] holds h after step t).
// ---------------------------------------------------------------------------
__global__ void __launch_bounds__(256)
out_gemm_tc(const float* __restrict__ Wd,
            const float* __restrict__ bd,
            float*       __restrict__ out) {
    unsigned* AhiW = (unsigned*)smem_raw;
    unsigned* AloW = AhiW + PLANE;
    unsigned* BhiW = AloW + PLANE;
    unsigned* BloW = BhiW + PLANE;

    const int tid  = threadIdx.x;
    const int r0   = blockIdx.x * 128;
    const int lane = tid & 31;
    const int wid  = tid >> 5;
    const int wr   = (wid & 3) * 32;
    const int wc   = (wid >> 2) * 64;
    const int g4r  = lane >> 2;
    const int lk   = lane & 3;
    const int lx2  = lk * 2;

    const int t_blk = r0 >> 8;
    const int b0    = r0 & 255;
    const unsigned* srcHi = g_hshi + (size_t)(t_blk + 1) * B_ * NW2;
    const unsigned* srcLo = g_hslo + (size_t)(t_blk + 1) * B_ * NW2;

    float acc[2][8][4];
#pragma unroll
    for (int f = 0; f < 2; f++)
#pragma unroll
        for (int s = 0; s < 8; s++)
#pragma unroll
            for (int i = 0; i < 4; i++) acc[f][s][i] = 0.f;

    const int arow = tid & 127;                    // one row per thread per plane
    const unsigned* asrc = (tid < 128 ? srcHi : srcLo) + (size_t)(b0 + arow) * NW2;
    unsigned* adst = (tid < 128 ? AhiW : AloW) + arow * GW;
    const int bc   = tid & 127;
    const int bkh  = tid >> 7;

    for (int kc = 0; kc < 8; kc++) {
        // stage A: pure copy of 32 packed words per row
#pragma unroll
        for (int q = 0; q < 8; q++)
            *(uint4*)(adst + q * 4) = __ldcg((const uint4*)(asrc + kc * 32 + q * 4));
        // stage B: Wd[k][v] -> Bs[col][k] (split)
#pragma unroll
        for (int kk = 0; kk < 16; kk++) {
            int k0 = kc * 64 + bkh * 32 + kk * 2;
            float a = Wd[(size_t)k0 * V_ + bc];
            float b = Wd[(size_t)(k0 + 1) * V_ + bc];
            __nv_bfloat16 ha, la, hb, lb;
            bf16_split(a, ha, la); bf16_split(b, hb, lb);
            int widx = bc * GW + bkh * 16 + kk;
            BhiW[widx] = pack_bf2(ha, hb);
            BloW[widx] = pack_bf2(la, lb);
        }
        __syncthreads();

        gemm_chunk(AhiW, AloW, BhiW, BloW, wr, wc, g4r, lk, acc);
        __syncthreads();
    }

#pragma unroll
    for (int f = 0; f < 2; f++) {
        int rlo = r0 + wr + f * 16 + g4r;
        int t0 = rlo >> 8,        bb0 = rlo & 255;
        int t1 = (rlo + 8) >> 8,  bb1 = (rlo + 8) & 255;
        size_t o0 = ((size_t)bb0 * T_ + t0) * V_;
        size_t o1 = ((size_t)bb1 * T_ + t1) * V_;
#pragma unroll
        for (int sub = 0; sub < 8; sub++) {
            int v = wc + sub * 8 + lx2;
            float2 bb = *(const float2*)(bd + v);
            *(float2*)(out + o0 + v) = make_float2(acc[f][sub][0] + bb.x, acc[f][sub][1] + bb.y);
            *(float2*)(out + o1 + v) = make_float2(acc[f][sub][2] + bb.x, acc[f][sub][3] + bb.y);
        }
    }
}

// ---------------------------------------------------------------------------
extern "C" void kernel_launch(void* const* d_in, const int* in_sizes, int n_in,
                              void* d_out, int out_size) {
    const int*   X    = (const int*)  d_in[0];
    const float* h0   = (const float*)d_in[1];
    const float* c0   = (const float*)d_in[2];
    const float* emb  = (const float*)d_in[3];
    const float* Wx   = (const float*)d_in[4];
    const float* Wh   = (const float*)d_in[5];
    const float* bias = (const float*)d_in[6];
    const float* Wd   = (const float*)d_in[7];
    const float* bd   = (const float*)d_in[8];
    float* out = (float*)d_out;

    cudaFuncSetAttribute(lstm_persistent, cudaFuncAttributeMaxDynamicSharedMemorySize, SMEM_TOTAL_LSTM);
    cudaFuncSetAttribute(input_gemm_tc,  cudaFuncAttributeMaxDynamicSharedMemorySize, SMEM_GEMM);
    cudaFuncSetAttribute(out_gemm_tc,    cudaFuncAttributeMaxDynamicSharedMemorySize, SMEM_GEMM);

    init_kernel<<<(B_ * NW2 + 255) / 256, 256>>>(h0);
    input_gemm_tc<<<dim3(G4 / 128, (T_ * B_) / 128), 256, SMEM_GEMM>>>(X, emb, Wx, bias);
    lstm_persistent<<<NBLK, 256, SMEM_TOTAL_LSTM>>>(Wh, c0);
    out_gemm_tc<<<(T_ * B_) / 128, 256, SMEM_GEMM>>>(Wd, bd, out);
}